// round 16
// baseline (speedup 1.0000x reference)
#include <cuda_runtime.h>
#include <cuda_fp16.h>
#include <cstdint>

// Problem: x [8,256,256,256] fp32, W [256,256], b [256]
//   u = x[:,:128], v = x[:,128:]; per-batch LayerNorm(v); v@W^T+b; out=u*(v+1)
// LayerNorm deferred to epilogue: vnorm@W^T = rstd*(v@W^T) - mean*rstd*rowsum(W)
#define B_              8
#define WD              256
#define ROWS_PER_BATCH  32768
#define M_TOTAL         262144
#define NV              8388608
#define BATCH_STRIDE    (2 * NV)
#define NCHUNK          512
#define EPS             1e-5f

#define BM   128          // rows per CTA
#define BN   128          // cols per CTA (half of WD)
#define NT   128          // 4 warps, warp tile 64x64
#define NMB  (M_TOTAL / BM)

// SMEM (bytes): c1 (128 f32) + 2 stages of (A 16KB + B 16KB).
// Epilogue staging (64 rows x 512B = 32KB) reuses stage 0 after its drain.
#define SMEM_C1    0
#define SMEM_ST(s) (1024 + (s) * 32768)
#define SMEM_AOF   0
#define SMEM_BOF   16384
#define SMEM_STG   1024
#define SMEM_TOTAL (1024 + 2 * 32768)   // 66560; x3 CTAs/SM fits 228KB

// ---------------- device scratch ----------------
__device__ float  g_partS[B_ * NCHUNK];
__device__ float  g_partQ[B_ * NCHUNK];
__device__ float  g_mean[B_];
__device__ float  g_rstd[B_];
__device__ float  g_Wsum[WD];
__device__ __half g_Wh[WD * WD];
__device__ __half g_vh[(size_t)M_TOTAL * WD];   // raw v, fp16 (written by pass1)

// ---------------- helpers ----------------
__device__ __forceinline__ uint32_t smem_u32(const void* p) {
    uint32_t a;
    asm("{ .reg .u64 t; cvta.to.shared.u64 t, %1; cvt.u32.u64 %0, t; }"
        : "=r"(a) : "l"(p));
    return a;
}
__device__ __forceinline__ uint32_t pack_f16x2(float lo, float hi) {
    uint32_t r;
    asm("cvt.rn.f16x2.f32 %0, %1, %2;" : "=r"(r) : "f"(hi), "f"(lo));
    return r;
}
__device__ __forceinline__ void cp16(uint32_t dst, const void* src) {
    asm volatile("cp.async.cg.shared.global [%0], [%1], 16;" :: "r"(dst), "l"(src));
}
#define CP_COMMIT() asm volatile("cp.async.commit_group;" ::: "memory")
#define CP_WAIT(n)  asm volatile("cp.async.wait_group %0;" :: "n"(n) : "memory")
__device__ __forceinline__ void ldsm_x4(uint32_t& r0, uint32_t& r1, uint32_t& r2,
                                        uint32_t& r3, uint32_t addr) {
    asm volatile("ldmatrix.sync.aligned.m8n8.x4.shared.b16 {%0,%1,%2,%3}, [%4];"
                 : "=r"(r0), "=r"(r1), "=r"(r2), "=r"(r3) : "r"(addr));
}
__device__ __forceinline__ void mma16816(float* d, const uint32_t* a,
                                         uint32_t b0, uint32_t b1) {
    asm volatile(
        "mma.sync.aligned.m16n8k16.row.col.f32.f16.f16.f32 "
        "{%0,%1,%2,%3}, {%4,%5,%6,%7}, {%8,%9}, {%0,%1,%2,%3};"
        : "+f"(d[0]), "+f"(d[1]), "+f"(d[2]), "+f"(d[3])
        : "r"(a[0]), "r"(a[1]), "r"(a[2]), "r"(a[3]), "r"(b0), "r"(b1));
}
// Stage fill for chunk kc (k=64): A (128x128B) + B (128x128B), one group.
__device__ __forceinline__ void issue_chunk(uint32_t stage, const char* vhp,
                                            const char* whp, int kc, int t) {
#pragma unroll
    for (int r = 0; r < 8; r++) {       // A: 1024 x 16B
        int idx = r * NT + t;
        int m = idx >> 3, ku = idx & 7;
        uint32_t off = (uint32_t)(m * 128) +
                       ((uint32_t)(ku * 16) ^ ((uint32_t)(m & 7) << 4));
        cp16(stage + SMEM_AOF + off, vhp + m * 512 + kc * 128 + ku * 16);
    }
#pragma unroll
    for (int r = 0; r < 8; r++) {       // B: 1024 x 16B
        int idx = r * NT + t;
        int o = idx >> 3, ku = idx & 7;
        uint32_t off = (uint32_t)(o * 128) +
                       ((uint32_t)(ku * 16) ^ ((uint32_t)(o & 7) << 4));
        cp16(stage + SMEM_BOF + off, whp + o * 512 + kc * 128 + ku * 16);
    }
    CP_COMMIT();
}

// ---------------- W prep: fp16 convert + row sums (tiny) ----------------
__global__ __launch_bounds__(256) void w_prep_kernel(const float* __restrict__ W) {
    const int o = blockIdx.x, t = threadIdx.x;
    float w = W[o * WD + t];
    g_Wh[o * WD + t] = __float2half_rn(w);
    float s = w;
#pragma unroll
    for (int off = 16; off > 0; off >>= 1) s += __shfl_xor_sync(0xffffffffu, s, off);
    __shared__ float ss[8];
    if ((t & 31) == 0) ss[t >> 5] = s;
    __syncthreads();
    if (t == 0) {
        float S = 0.f;
#pragma unroll
        for (int w8 = 0; w8 < 8; w8++) S += ss[w8];
        g_Wsum[o] = S;
    }
}

// ---------------- pass 1: stats + v -> fp16 copy ----------------
__global__ __launch_bounds__(256) void reduce_pass1(const float* __restrict__ x) {
    const int b = blockIdx.y;
    const int chunk = blockIdx.x;
    const float4* v4 =
        reinterpret_cast<const float4*>(x + (size_t)b * BATCH_STRIDE + NV);
    uint2* vh2 = reinterpret_cast<uint2*>(g_vh + (size_t)b * NV);
    const int base = chunk * 4096 + threadIdx.x;
    float s = 0.f, q = 0.f;
#pragma unroll
    for (int i = 0; i < 16; i++) {
        float4 t = v4[base + i * 256];
        s += (t.x + t.y) + (t.z + t.w);
        q += t.x * t.x + t.y * t.y + t.z * t.z + t.w * t.w;
        vh2[base + i * 256] =
            make_uint2(pack_f16x2(t.x, t.y), pack_f16x2(t.z, t.w));
    }
#pragma unroll
    for (int off = 16; off > 0; off >>= 1) {
        s += __shfl_xor_sync(0xffffffffu, s, off);
        q += __shfl_xor_sync(0xffffffffu, q, off);
    }
    __shared__ float ss[8], qs[8];
    const int warp = threadIdx.x >> 5, lane = threadIdx.x & 31;
    if (lane == 0) { ss[warp] = s; qs[warp] = q; }
    __syncthreads();
    if (threadIdx.x == 0) {
        float S = 0.f, Q = 0.f;
#pragma unroll
        for (int w = 0; w < 8; w++) { S += ss[w]; Q += qs[w]; }
        g_partS[b * NCHUNK + chunk] = S;
        g_partQ[b * NCHUNK + chunk] = Q;
    }
}

__global__ __launch_bounds__(256) void reduce_pass2() {
    const int b = blockIdx.x;
    float s = g_partS[b * NCHUNK + threadIdx.x] +
              g_partS[b * NCHUNK + 256 + threadIdx.x];
    float q = g_partQ[b * NCHUNK + threadIdx.x] +
              g_partQ[b * NCHUNK + 256 + threadIdx.x];
#pragma unroll
    for (int off = 16; off > 0; off >>= 1) {
        s += __shfl_xor_sync(0xffffffffu, s, off);
        q += __shfl_xor_sync(0xffffffffu, q, off);
    }
    __shared__ float ss[8], qs[8];
    const int warp = threadIdx.x >> 5, lane = threadIdx.x & 31;
    if (lane == 0) { ss[warp] = s; qs[warp] = q; }
    __syncthreads();
    if (threadIdx.x == 0) {
        float S = 0.f, Q = 0.f;
#pragma unroll
        for (int w = 0; w < 8; w++) { S += ss[w]; Q += qs[w]; }
        const float inv_n = 1.0f / (float)NV;
        float mean = S * inv_n;
        float var = Q * inv_n - mean * mean;
        g_mean[b] = mean;
        g_rstd[b] = rsqrtf(var + EPS);
    }
}

// ---------------- fused GEMM + gating ----------------
// CTA 128x128, 4 warps (warp tile 64x64 -> 0.1875 ldsm/MMA), 3 CTAs/SM.
// A+B streamed in 4 k=64 chunks, 2-stage cp.async, full overlap.
extern __shared__ char smc[];

__global__ __launch_bounds__(NT, 3) void fused_kernel(
    const float* __restrict__ x, const float* __restrict__ bias,
    float* __restrict__ out) {
    const uint32_t sb = smem_u32(smc);
    const int t = threadIdx.x;
    const int wid = t >> 5, lane = t & 31;

    const int nb = blockIdx.x;              // 0/1: which 128-col half of W
    const int row0 = blockIdx.y * BM;
    const int batch = row0 >> 15;
    const int rlocal0 = row0 & (ROWS_PER_BATCH - 1);
    const float mean = g_mean[batch];
    const float rstd = g_rstd[batch];

    const char* vhp = reinterpret_cast<const char*>(g_vh + (size_t)row0 * WD);
    const char* whp =
        reinterpret_cast<const char*>(g_Wh + (size_t)(nb * BN) * WD);

    // chunks 0,1 into stages 0,1
    issue_chunk(sb + SMEM_ST(0), vhp, whp, 0, t);
    issue_chunk(sb + SMEM_ST(1), vhp, whp, 1, t);

    // c1[o] = bias[o] + 1 - mean*rstd*Wsum[o]  (all 128 threads, t<BN)
    {
        int col = nb * BN + t;
        reinterpret_cast<float*>(smc + SMEM_C1)[t] =
            bias[col] + 1.f - mean * rstd * g_Wsum[col];
    }

    const int wm = (wid & 1) * 64;          // 2 m-warps
    const int wn = (wid >> 1) * 64;         // 2 n-warps
    const int lg = lane >> 3, lr = lane & 7;

    float acc[4][8][4];
#pragma unroll
    for (int i = 0; i < 4; i++)
#pragma unroll
        for (int j = 0; j < 8; j++)
#pragma unroll
            for (int q = 0; q < 4; q++) acc[i][j][q] = 0.f;

    // 2-stage ledger: at c outstanding = [c, c+1]; wait(1) readies chunk c.
    // Chunk c+2 is issued after compute c (buffer c%2 drained by that sync),
    // so its load overlaps compute c+1.
#pragma unroll 1
    for (int c = 0; c < 4; c++) {
        if (c < 3) CP_WAIT(1); else CP_WAIT(0);
        __syncthreads();   // chunk c visible to all warps

        const uint32_t As = sb + SMEM_ST(c & 1) + SMEM_AOF;
        const uint32_t Bs = sb + SMEM_ST(c & 1) + SMEM_BOF;
#pragma unroll
        for (int ks = 0; ks < 4; ks++) {
            const int kl = ks * 16;
            uint32_t af[4][4];
#pragma unroll
            for (int i = 0; i < 4; i++) {
                int am = wm + i * 16 + ((lg & 1) << 3) + lr;
                int ak = kl + ((lg >> 1) << 3);
                uint32_t off = (uint32_t)(am * 128) +
                               ((uint32_t)(ak * 2) ^ ((uint32_t)(am & 7) << 4));
                ldsm_x4(af[i][0], af[i][1], af[i][2], af[i][3], As + off);
            }
#pragma unroll
            for (int p = 0; p < 4; p++) {
                int bn = wn + p * 16 + ((lg >> 1) << 3) + lr;
                int bk = kl + ((lg & 1) << 3);
                uint32_t off = (uint32_t)(bn * 128) +
                               ((uint32_t)(bk * 2) ^ ((uint32_t)(bn & 7) << 4));
                uint32_t b0, b1, b2, b3;
                ldsm_x4(b0, b1, b2, b3, Bs + off);
#pragma unroll
                for (int i = 0; i < 4; i++) {
                    mma16816(acc[i][p * 2 + 0], af[i], b0, b1);
                    mma16816(acc[i][p * 2 + 1], af[i], b2, b3);
                }
            }
        }
        __syncthreads();   // all warps done with buffer c%2
        if (c < 2)
            issue_chunk(sb + SMEM_ST(c & 1), vhp, whp, c + 2, t);
    }

    // ---- epilogue: 2 passes of 64 rows, fp32 staging, coalesced gating ----
    {
        const int qr = lane >> 2;
        const int qc = (lane & 3) * 2;
        const int colbase = nb * BN;
        const int lane5 = t & 31, rg = t >> 5;   // rg 0..3
        const float* c1 = reinterpret_cast<const float*>(smc + SMEM_C1);
        const float* uBase =
            x + (size_t)batch * BATCH_STRIDE + (size_t)rlocal0 * WD + colbase;
        const float4 c4 = *reinterpret_cast<const float4*>(c1 + lane5 * 4);

#pragma unroll 1
        for (int pass = 0; pass < 2; pass++) {
            __syncthreads();
            if ((wm >> 6) == pass) {    // warps owning rows [pass*64, +64)
#pragma unroll
                for (int i = 0; i < 4; i++)
#pragma unroll
                    for (int half = 0; half < 2; half++) {
                        const int row = i * 16 + half * 8 + qr;   // 0..63
#pragma unroll
                        for (int j = 0; j < 8; j++) {
                            const int col = wn + j * 8 + qc;
                            float2 dv = make_float2(acc[i][j][half * 2 + 0],
                                                    acc[i][j][half * 2 + 1]);
                            *reinterpret_cast<float2*>(
                                smc + SMEM_STG + row * 512 +
                                ((col * 4) ^ ((row & 7) << 4))) = dv;
                        }
                    }
            }
            __syncthreads();
#pragma unroll
            for (int it = 0; it < 16; it++) {
                const int row = it * 4 + rg;         // 0..63
                const int grow = pass * 64 + row;
                float4 d4 = *reinterpret_cast<const float4*>(
                    smc + SMEM_STG + row * 512 +
                    ((lane5 * 16) ^ ((row & 7) << 4)));
                float4 u4 = *reinterpret_cast<const float4*>(
                    uBase + (size_t)grow * WD + lane5 * 4);
                float4 r;
                r.x = u4.x * fmaf(d4.x, rstd, c4.x);
                r.y = u4.y * fmaf(d4.y, rstd, c4.y);
                r.z = u4.z * fmaf(d4.z, rstd, c4.z);
                r.w = u4.w * fmaf(d4.w, rstd, c4.w);
                *reinterpret_cast<float4*>(
                    out + (size_t)(row0 + grow) * WD + colbase + lane5 * 4) = r;
            }
        }
    }
}

// ---------------- launch ----------------
extern "C" void kernel_launch(void* const* d_in, const int* in_sizes, int n_in,
                              void* d_out, int out_size) {
    const float* x = (const float*)d_in[0];
    const float* W = (const float*)d_in[1];
    const float* b = (const float*)d_in[2];
    float* out = (float*)d_out;

    w_prep_kernel<<<WD, 256>>>(W);
    reduce_pass1<<<dim3(NCHUNK, B_), 256>>>(x);
    reduce_pass2<<<B_, 256>>>();

    cudaFuncSetAttribute(fused_kernel,
                         cudaFuncAttributeMaxDynamicSharedMemorySize, SMEM_TOTAL);
    fused_kernel<<<dim3(2, NMB), NT, SMEM_TOTAL>>>(x, b, out);
}

// round 17
// speedup vs baseline: 1.1958x; 1.1958x over previous
#include <cuda_runtime.h>
#include <cuda_fp16.h>
#include <cstdint>

// Problem: x [8,256,256,256] fp32, W [256,256], b [256]
//   u = x[:,:128], v = x[:,128:]; per-batch LayerNorm(v); v@W^T+b; out=u*(v+1)
// LayerNorm deferred to epilogue: vnorm@W^T = rstd*(v@W^T) - mean*rstd*rowsum(W)
#define B_              8
#define WD              256
#define ROWS_PER_BATCH  32768
#define M_TOTAL         262144
#define NV              8388608
#define BATCH_STRIDE    (2 * NV)
#define NCHUNK          512
#define EPS             1e-5f

#define BM   128          // rows per CTA
#define BN   128          // cols per CTA (half of WD)
#define NT   256          // 8 warps, warp tile 32x64 (R10 optimum)
#define NMB  (M_TOTAL / BM)

// SMEM (bytes): c1 (128 f32), A 3-stage (16KB each), B resident (64KB).
// Epilogue: P staged in stage 0 (32 rows x 512B); u prefetched into stages 1+2.
#define SMEM_C1    0
#define SMEM_A(s)  (1024 + (s) * 16384)
#define SMEM_B     (1024 + 3 * 16384)
#define SMEM_TOTAL (SMEM_B + 65536)      // 115712; x2 CTAs/SM = full carveout

// ---------------- device scratch ----------------
__device__ float  g_partS[B_ * NCHUNK];
__device__ float  g_partQ[B_ * NCHUNK];
__device__ float  g_mean[B_];
__device__ float  g_rstd[B_];
__device__ float  g_Wsum[WD];
__device__ __half g_Wh[WD * WD];
__device__ __half g_vh[(size_t)M_TOTAL * WD];   // raw v, fp16 (written by pass1)

// ---------------- helpers ----------------
__device__ __forceinline__ uint32_t smem_u32(const void* p) {
    uint32_t a;
    asm("{ .reg .u64 t; cvta.to.shared.u64 t, %1; cvt.u32.u64 %0, t; }"
        : "=r"(a) : "l"(p));
    return a;
}
__device__ __forceinline__ uint32_t pack_f16x2(float lo, float hi) {
    uint32_t r;
    asm("cvt.rn.f16x2.f32 %0, %1, %2;" : "=r"(r) : "f"(hi), "f"(lo));
    return r;
}
__device__ __forceinline__ void cp16(uint32_t dst, const void* src) {
    asm volatile("cp.async.cg.shared.global [%0], [%1], 16;" :: "r"(dst), "l"(src));
}
#define CP_COMMIT() asm volatile("cp.async.commit_group;" ::: "memory")
#define CP_WAIT(n)  asm volatile("cp.async.wait_group %0;" :: "n"(n) : "memory")
__device__ __forceinline__ void ldsm_x4(uint32_t& r0, uint32_t& r1, uint32_t& r2,
                                        uint32_t& r3, uint32_t addr) {
    asm volatile("ldmatrix.sync.aligned.m8n8.x4.shared.b16 {%0,%1,%2,%3}, [%4];"
                 : "=r"(r0), "=r"(r1), "=r"(r2), "=r"(r3) : "r"(addr));
}
__device__ __forceinline__ void mma16816(float* d, const uint32_t* a,
                                         uint32_t b0, uint32_t b1) {
    asm volatile(
        "mma.sync.aligned.m16n8k16.row.col.f32.f16.f16.f32 "
        "{%0,%1,%2,%3}, {%4,%5,%6,%7}, {%8,%9}, {%0,%1,%2,%3};"
        : "+f"(d[0]), "+f"(d[1]), "+f"(d[2]), "+f"(d[3])
        : "r"(a[0]), "r"(a[1]), "r"(a[2]), "r"(a[3]), "r"(b0), "r"(b1));
}
// A-chunk stage fill (R10): chunk kc of block at vhp -> stage buffer
__device__ __forceinline__ void issue_a_chunk(uint32_t stage_base,
                                              const char* vhp, int kc, int t) {
#pragma unroll
    for (int r = 0; r < 4; r++) {
        int idx = r * NT + t;
        int m = idx >> 3, ku = idx & 7;     // 128B rows (k=64)
        uint32_t off = (uint32_t)(m * 128 + ku * 16) ^ ((uint32_t)(m & 7) << 4);
        cp16(stage_base + off, vhp + m * 512 + kc * 128 + ku * 16);
    }
    CP_COMMIT();
}
// u prefetch: 32 fp32 rows (512B each) -> stage, swizzled; one commit group.
__device__ __forceinline__ void issue_u32(uint32_t stage, const float* u0,
                                          int t) {
#pragma unroll
    for (int r = 0; r < 4; r++) {
        int idx = r * NT + t;               // 1024 x 16B
        int row = idx >> 5, ku = idx & 31;
        uint32_t off = (uint32_t)(row * 512) +
                       ((uint32_t)(ku * 16) ^ ((uint32_t)(row & 7) << 4));
        cp16(stage + off,
             reinterpret_cast<const char*>(u0 + (size_t)row * WD) + ku * 16);
    }
    CP_COMMIT();
}

// ---------------- W prep: fp16 convert + row sums (tiny) ----------------
__global__ __launch_bounds__(256) void w_prep_kernel(const float* __restrict__ W) {
    const int o = blockIdx.x, t = threadIdx.x;
    float w = W[o * WD + t];
    g_Wh[o * WD + t] = __float2half_rn(w);
    float s = w;
#pragma unroll
    for (int off = 16; off > 0; off >>= 1) s += __shfl_xor_sync(0xffffffffu, s, off);
    __shared__ float ss[8];
    if ((t & 31) == 0) ss[t >> 5] = s;
    __syncthreads();
    if (t == 0) {
        float S = 0.f;
#pragma unroll
        for (int w8 = 0; w8 < 8; w8++) S += ss[w8];
        g_Wsum[o] = S;
    }
}

// ---------------- pass 1: stats + v -> fp16 copy ----------------
__global__ __launch_bounds__(256) void reduce_pass1(const float* __restrict__ x) {
    const int b = blockIdx.y;
    const int chunk = blockIdx.x;
    const float4* v4 =
        reinterpret_cast<const float4*>(x + (size_t)b * BATCH_STRIDE + NV);
    uint2* vh2 = reinterpret_cast<uint2*>(g_vh + (size_t)b * NV);
    const int base = chunk * 4096 + threadIdx.x;
    float s = 0.f, q = 0.f;
#pragma unroll
    for (int i = 0; i < 16; i++) {
        float4 t = v4[base + i * 256];
        s += (t.x + t.y) + (t.z + t.w);
        q += t.x * t.x + t.y * t.y + t.z * t.z + t.w * t.w;
        vh2[base + i * 256] =
            make_uint2(pack_f16x2(t.x, t.y), pack_f16x2(t.z, t.w));
    }
#pragma unroll
    for (int off = 16; off > 0; off >>= 1) {
        s += __shfl_xor_sync(0xffffffffu, s, off);
        q += __shfl_xor_sync(0xffffffffu, q, off);
    }
    __shared__ float ss[8], qs[8];
    const int warp = threadIdx.x >> 5, lane = threadIdx.x & 31;
    if (lane == 0) { ss[warp] = s; qs[warp] = q; }
    __syncthreads();
    if (threadIdx.x == 0) {
        float S = 0.f, Q = 0.f;
#pragma unroll
        for (int w = 0; w < 8; w++) { S += ss[w]; Q += qs[w]; }
        g_partS[b * NCHUNK + chunk] = S;
        g_partQ[b * NCHUNK + chunk] = Q;
    }
}

__global__ __launch_bounds__(256) void reduce_pass2() {
    const int b = blockIdx.x;
    float s = g_partS[b * NCHUNK + threadIdx.x] +
              g_partS[b * NCHUNK + 256 + threadIdx.x];
    float q = g_partQ[b * NCHUNK + threadIdx.x] +
              g_partQ[b * NCHUNK + 256 + threadIdx.x];
#pragma unroll
    for (int off = 16; off > 0; off >>= 1) {
        s += __shfl_xor_sync(0xffffffffu, s, off);
        q += __shfl_xor_sync(0xffffffffu, q, off);
    }
    __shared__ float ss[8], qs[8];
    const int warp = threadIdx.x >> 5, lane = threadIdx.x & 31;
    if (lane == 0) { ss[warp] = s; qs[warp] = q; }
    __syncthreads();
    if (threadIdx.x == 0) {
        float S = 0.f, Q = 0.f;
#pragma unroll
        for (int w = 0; w < 8; w++) { S += ss[w]; Q += qs[w]; }
        const float inv_n = 1.0f / (float)NV;
        float mean = S * inv_n;
        float var = Q * inv_n - mean * mean;
        g_mean[b] = mean;
        g_rstd[b] = rsqrtf(var + EPS);
    }
}

// ---------------- fused GEMM + gating (R10 base + u prefetch epilogue) ----
extern __shared__ char smc[];

__global__ __launch_bounds__(NT, 2) void fused_kernel(
    const float* __restrict__ x, const float* __restrict__ bias,
    float* __restrict__ out) {
    const uint32_t sb = smem_u32(smc);
    const int t = threadIdx.x;
    const int wid = t >> 5, lane = t & 31;

    const int nb = blockIdx.x;              // 0/1: which 128-col half of W
    const int row0 = blockIdx.y * BM;
    const int batch = row0 >> 15;
    const int rlocal0 = row0 & (ROWS_PER_BATCH - 1);
    const float mean = g_mean[batch];
    const float rstd = g_rstd[batch];

    const char* vhp = reinterpret_cast<const char*>(g_vh + (size_t)row0 * WD);
    const char* whp =
        reinterpret_cast<const char*>(g_Wh + (size_t)(nb * BN) * WD);
    const int colbase = nb * BN;
    const float* uBase =
        x + (size_t)batch * BATCH_STRIDE + (size_t)rlocal0 * WD + colbase;

    // c1[o] = bias[o] + 1 - mean*rstd*Wsum[o]
    if (t < BN) {
        int col = colbase + t;
        reinterpret_cast<float*>(smc + SMEM_C1)[t] =
            bias[col] + 1.f - mean * rstd * g_Wsum[col];
    }

    // group 0: B resident (4096 x 16B) + A chunk 0
#pragma unroll
    for (int r = 0; r < 16; r++) {
        int idx = r * NT + t;
        int o = idx >> 5, ku = idx & 31;    // 512B rows (k=256)
        uint32_t off = (uint32_t)(o * 512 + ku * 16) ^ ((uint32_t)(o & 7) << 4);
        cp16(sb + SMEM_B + off, whp + o * 512 + ku * 16);
    }
#pragma unroll
    for (int r = 0; r < 4; r++) {
        int idx = r * NT + t;
        int m = idx >> 3, ku = idx & 7;
        uint32_t off = (uint32_t)(m * 128 + ku * 16) ^ ((uint32_t)(m & 7) << 4);
        cp16(sb + SMEM_A(0) + off, vhp + m * 512 + ku * 16);
    }
    CP_COMMIT();
    issue_a_chunk(sb + SMEM_A(1), vhp, 1, t);   // group 1

    const int wm = (wid & 3) * 32;          // warp m base (4 warps)
    const int wn = (wid >> 2) * 64;         // warp n base (2 warps)
    const int lg = lane >> 3, lr = lane & 7;

    float acc[2][8][4];
#pragma unroll
    for (int i = 0; i < 2; i++)
#pragma unroll
        for (int j = 0; j < 8; j++)
#pragma unroll
            for (int q = 0; q < 4; q++) acc[i][j][q] = 0.f;

#pragma unroll 1
    for (int c = 0; c < 4; c++) {
        if (c < 3) CP_WAIT(1); else CP_WAIT(0);
        __syncthreads();   // chunk c ready; stage (c+2)%3 drained

        if (c < 2) {
            issue_a_chunk(sb + SMEM_A((c + 2) % 3), vhp, c + 2, t);
        } else if (c == 3) {
            // stages 1,2 dead (chunks 1,2 consumed): prefetch u rows 0..63
            issue_u32(sb + SMEM_A(1), uBase, t);
            issue_u32(sb + SMEM_A(2), uBase + (size_t)32 * WD, t);
        }

        const uint32_t Ab = sb + SMEM_A(c % 3);
#pragma unroll
        for (int ks = 0; ks < 4; ks++) {
            const int kl = ks * 16;
            uint32_t af[2][4];
#pragma unroll
            for (int i = 0; i < 2; i++) {
                int am = wm + i * 16 + ((lg & 1) << 3) + lr;
                int ak = kl + ((lg >> 1) << 3);
                uint32_t off = (uint32_t)(am * 128 + ak * 2) ^ ((uint32_t)(am & 7) << 4);
                ldsm_x4(af[i][0], af[i][1], af[i][2], af[i][3], Ab + off);
            }
#pragma unroll
            for (int p = 0; p < 4; p++) {
                int bn = wn + p * 16 + ((lg >> 1) << 3) + lr;
                int bk = c * 64 + kl + ((lg & 1) << 3);
                uint32_t off = (uint32_t)(bn * 512 + bk * 2) ^ ((uint32_t)(bn & 7) << 4);
                uint32_t b0, b1, b2, b3;
                ldsm_x4(b0, b1, b2, b3, sb + SMEM_B + off);
#pragma unroll
                for (int i = 0; i < 2; i++) {
                    mma16816(acc[i][p * 2 + 0], af[i], b0, b1);
                    mma16816(acc[i][p * 2 + 1], af[i], b2, b3);
                }
            }
        }
    }

    // ---- epilogue: 4 passes of 32 rows; P in stage 0, u from stages 1/2 ----
    // u stage for pass p: p0,p2 -> stage1 ; p1,p3 -> stage2 (ping-pong refill).
    {
        const int qr = lane >> 2;
        const int qc = (lane & 3) * 2;
        const int lane5 = t & 31, rg = t >> 5;   // rg 0..7
        const float* c1 = reinterpret_cast<const float*>(smc + SMEM_C1);
        const float4 c4 = *reinterpret_cast<const float4*>(c1 + lane5 * 4);

#pragma unroll 1
        for (int pass = 0; pass < 4; pass++) {
            __syncthreads();   // stage0 free; previous gating done
            if (pass == 1)     // stage1 (u rows 0-31) consumed -> refill 64-95
                issue_u32(sb + SMEM_A(1), uBase + (size_t)64 * WD, t);
            if (pass == 2)     // stage2 (u rows 32-63) consumed -> refill 96-127
                issue_u32(sb + SMEM_A(2), uBase + (size_t)96 * WD, t);

            if ((wm >> 5) == pass) {   // 2 warps own this 32-row band
#pragma unroll
                for (int i = 0; i < 2; i++)
#pragma unroll
                    for (int half = 0; half < 2; half++) {
                        const int row = i * 16 + half * 8 + qr;   // 0..31
#pragma unroll
                        for (int j = 0; j < 8; j++) {
                            const int col = wn + j * 8 + qc;
                            float2 dv = make_float2(acc[i][j][half * 2 + 0],
                                                    acc[i][j][half * 2 + 1]);
                            *reinterpret_cast<float2*>(
                                smc + SMEM_A(0) + row * 512 +
                                ((col * 4) ^ ((row & 7) << 4))) = dv;
                        }
                    }
            }
            __syncthreads();
            if (pass == 0) CP_WAIT(0);      // u rows 0-63 landed
            if (pass == 2) CP_WAIT(1);      // u rows 64-95 landed
            if (pass == 3) CP_WAIT(0);      // u rows 96-127 landed

            const uint32_t uStage = sb + ((pass & 1) ? SMEM_A(2) : SMEM_A(1));
#pragma unroll
            for (int it = 0; it < 4; it++) {
                const int row = it * 8 + rg;         // 0..31
                const uint32_t swz = (uint32_t)((lane5 * 16) ^ ((row & 7) << 4));
                float4 d4 = *reinterpret_cast<const float4*>(
                    smc + (SMEM_A(0) - 0) + row * 512 + swz);
                float4 u4 = *reinterpret_cast<const float4*>(
                    reinterpret_cast<const char*>(smc) +
                    (uStage - sb) + row * 512 + swz);
                float4 r;
                r.x = u4.x * fmaf(d4.x, rstd, c4.x);
                r.y = u4.y * fmaf(d4.y, rstd, c4.y);
                r.z = u4.z * fmaf(d4.z, rstd, c4.z);
                r.w = u4.w * fmaf(d4.w, rstd, c4.w);
                *reinterpret_cast<float4*>(
                    out + (size_t)(row0 + pass * 32 + row) * WD + colbase +
                    lane5 * 4) = r;
            }
        }
    }
}

// ---------------- launch ----------------
extern "C" void kernel_launch(void* const* d_in, const int* in_sizes, int n_in,
                              void* d_out, int out_size) {
    const float* x = (const float*)d_in[0];
    const float* W = (const float*)d_in[1];
    const float* b = (const float*)d_in[2];
    float* out = (float*)d_out;

    w_prep_kernel<<<WD, 256>>>(W);
    reduce_pass1<<<dim3(NCHUNK, B_), 256>>>(x);
    reduce_pass2<<<B_, 256>>>();

    cudaFuncSetAttribute(fused_kernel,
                         cudaFuncAttributeMaxDynamicSharedMemorySize, SMEM_TOTAL);
    fused_kernel<<<dim3(2, NMB), NT, SMEM_TOTAL>>>(x, b, out);
}